// round 4
// baseline (speedup 1.0000x reference)
#include <cuda_runtime.h>

#define HWSZ   262144
#define NIMG   128
#define AXK    26214
#define SEG    16
#define CAPB   4096
#define CAPI   (SEG*CAPB)
#define SELCAP 4096
#define R_HI   260
#define R_LO   560

// ---------------- static scratch ----------------
__device__ unsigned g_cand[(size_t)2 * NIMG * CAPI];   // 64 MB
__device__ unsigned g_bhist[2 * NIMG * 256];           // per-image 256-bin bucket hist
__device__ unsigned g_cnt[2 * NIMG][SEG];
__device__ unsigned g_above[2 * NIMG];
__device__ unsigned g_hi[2 * NIMG], g_lo[2 * NIMG], g_thr[2 * NIMG];
__device__ double   g_acc;

// Bit-identical squared Roberts magnitude everywhere (fixed op order).
__device__ __forceinline__ float m2_one(float a, float b, float c, float d) {
    float gx = a - d, gy = b - c;
    return fmaf(gx, gx, fmaf(gy, gy, 1e-12f));
}

// Uniform bucket of v in (lo, hi], width = hi-lo > 0. Identical in K2/K3.
__device__ __forceinline__ unsigned bucket_of(unsigned v, unsigned lo, unsigned width) {
    return (unsigned)((((unsigned long long)(v - lo - 1u)) << 8) / width);
}

struct Quad { float4 v0, v1; float x4, y4; };

__device__ __forceinline__ Quad load_quad(const float* __restrict__ img, int p, int lane) {
    Quad q;
    int i = p >> 9, j = p & 511;
    q.v0 = __ldg((const float4*)(img + p));
    bool lastrow = (i == 511);
    q.v1 = lastrow ? make_float4(0.f, 0.f, 0.f, 0.f)
                   : __ldg((const float4*)(img + p + 512));
    q.x4 = __shfl_down_sync(0xffffffffu, q.v0.x, 1);
    q.y4 = __shfl_down_sync(0xffffffffu, q.v1.x, 1);
    if (lane == 31) {
        bool hn = (j + 4) < 512;
        q.x4 = hn ? __ldg(img + p + 4) : 0.0f;
        q.y4 = (hn && !lastrow) ? __ldg(img + p + 516) : 0.0f;
    }
    return q;
}

__device__ __forceinline__ void quad_m2(const Quad& q, float m2[4]) {
    m2[0] = m2_one(q.v0.x, q.v0.y, q.v1.x, q.v1.y);
    m2[1] = m2_one(q.v0.y, q.v0.z, q.v1.y, q.v1.z);
    m2[2] = m2_one(q.v0.z, q.v0.w, q.v1.z, q.v1.w);
    m2[3] = m2_one(q.v0.w, q.x4,   q.v1.w, q.y4);
}

// inclusive suffix sum over 256 shared entries (256 threads)
__device__ __forceinline__ void suffix256(volatile unsigned* s, int tid) {
    #pragma unroll
    for (int off = 1; off < 256; off <<= 1) {
        unsigned add = (tid + off < 256) ? s[tid + off] : 0u;
        __syncthreads();
        s[tid] += add;
        __syncthreads();
    }
}

// ---------------- K0: zero ----------------
__global__ void k_zero() {
    int t = blockIdx.x * 256 + threadIdx.x;
    if (t < 2 * NIMG * 256) g_bhist[t] = 0;
    if (t < 2 * NIMG * SEG) ((unsigned*)g_cnt)[t] = 0;
    if (t < 2 * NIMG) g_above[t] = 0;
    if (t == 0) g_acc = 0.0;
}

// ---------------- K1: sampled bracket via 4-round radix on 4096 samples ------
__global__ void k_bracket(const float* __restrict__ tgt, const float* __restrict__ prd) {
    __shared__ unsigned sval[4096];
    __shared__ unsigned hist[256];
    __shared__ unsigned s_d;
    int n = blockIdx.x, sel = blockIdx.y;
    const float* img = (sel ? prd : tgt) + (size_t)n * HWSZ;
    int tid = threadIdx.x, lane = tid & 31, wid = tid >> 5;

    #pragma unroll
    for (int k = 0; k < 4; k++) {
        int c   = k * 8 + wid;
        int row = (c * 509) & 511;
        int col = (c & 3) * 128;
        int p   = row * 512 + col + lane * 4;
        Quad q = load_quad(img, p, lane);
        float m2[4]; quad_m2(q, m2);
        int s = c * 128 + lane * 4;
        sval[s + 0] = __float_as_uint(m2[0]);
        sval[s + 1] = __float_as_uint(m2[1]);
        sval[s + 2] = __float_as_uint(m2[2]);
        sval[s + 3] = __float_as_uint(m2[3]);
    }
    __syncthreads();

    unsigned res[2]; const int ranks[2] = { R_HI, R_LO };
    for (int r = 0; r < 2; r++) {
        unsigned prefix = 0, rank = (unsigned)ranks[r];
        for (int shift = 24; shift >= 0; shift -= 8) {
            hist[tid] = 0;
            __syncthreads();
            unsigned hmask = (shift == 24) ? 0u : (0xFFFFFFFFu << (shift + 8));
            #pragma unroll
            for (int k = 0; k < 16; k++) {
                unsigned v = sval[k * 256 + tid];
                if ((v & hmask) == prefix) atomicAdd(&hist[(v >> shift) & 255u], 1u);
            }
            __syncthreads();
            suffix256(hist, tid);
            unsigned sufd  = hist[tid];
            unsigned sufd1 = (tid < 255) ? hist[tid + 1] : 0u;
            if (sufd >= rank && sufd1 < rank) s_d = (unsigned)tid;
            __syncthreads();
            unsigned d = s_d;
            rank -= (d < 255) ? hist[d + 1] : 0u;
            prefix |= d << shift;
            __syncthreads();
        }
        res[r] = prefix;
    }
    if (tid == 0) {
        int ns = sel * NIMG + n;
        g_hi[ns] = res[0];
        g_lo[ns] = res[1];
    }
}

// ---------------- K2: count above-hi + compaction + bucket histogram ---------
__global__ void __launch_bounds__(256) k_count(const float* __restrict__ tgt,
                                               const float* __restrict__ prd) {
    __shared__ unsigned scnt;
    __shared__ unsigned sred[8];
    __shared__ unsigned shist[256];
    int seg = blockIdx.x, n = blockIdx.y, sel = blockIdx.z;
    int ns = sel * NIMG + n;
    const float* img = (sel ? prd : tgt) + (size_t)n * HWSZ;
    unsigned hi = g_hi[ns], lo = g_lo[ns];
    unsigned width = hi - lo;
    int tid = threadIdx.x, lane = tid & 31;
    if (tid == 0) scnt = 0;
    shist[tid] = 0;
    __syncthreads();
    unsigned* seg_out = g_cand + (size_t)ns * CAPI + (size_t)seg * CAPB;
    unsigned above = 0;
    int base = seg * (HWSZ / SEG);

    #pragma unroll 2
    for (int it = 0; it < (HWSZ / SEG) / 1024; it++) {
        int p = base + it * 1024 + tid * 4;
        Quad q = load_quad(img, p, lane);
        float m2[4]; quad_m2(q, m2);
        unsigned vb[4], c = 0; bool isc[4];
        #pragma unroll
        for (int k = 0; k < 4; k++) {
            vb[k] = __float_as_uint(m2[k]);
            above += (vb[k] > hi);
            isc[k] = (vb[k] > lo) && (vb[k] <= hi);
            c += isc[k];
        }
        unsigned inc = c;
        #pragma unroll
        for (int o = 1; o < 32; o <<= 1) {
            unsigned t = __shfl_up_sync(0xffffffffu, inc, o);
            if (lane >= o) inc += t;
        }
        unsigned tot = __shfl_sync(0xffffffffu, inc, 31);
        if (tot) {
            unsigned bb = 0;
            if (lane == 31) bb = atomicAdd(&scnt, tot);
            bb = __shfl_sync(0xffffffffu, bb, 31);
            unsigned off = bb + inc - c;
            #pragma unroll
            for (int k = 0; k < 4; k++)
                if (isc[k]) {
                    if (off < CAPB) {
                        seg_out[off] = vb[k];
                        atomicAdd(&shist[bucket_of(vb[k], lo, width)], 1u);
                    }
                    off++;
                }
        }
    }
    #pragma unroll
    for (int o = 16; o; o >>= 1) above += __shfl_down_sync(0xffffffffu, above, o);
    if (lane == 0) sred[tid >> 5] = above;
    __syncthreads();
    if (shist[tid]) atomicAdd(&g_bhist[ns * 256 + tid], shist[tid]);
    if (tid == 0) {
        unsigned t = 0;
        #pragma unroll
        for (int w = 0; w < 8; w++) t += sred[w];
        atomicAdd(&g_above[ns], t);
        g_cnt[ns][seg] = min(scnt, (unsigned)CAPB);
    }
}

// ---------------- K3: exact select via bucket hist + single candidate pass ---
__global__ void k_select() {
    __shared__ unsigned hist[256];
    __shared__ unsigned sbuf[SELCAP];
    __shared__ unsigned cnts[SEG];
    __shared__ unsigned s_d, s_cnt;
    int ns = blockIdx.x, tid = threadIdx.x;
    if (tid < SEG) cnts[tid] = min(g_cnt[ns][tid], (unsigned)CAPB);
    if (tid == 0) s_cnt = 0;
    hist[tid] = g_bhist[ns * 256 + tid];
    __syncthreads();
    unsigned above = g_above[ns];
    long j = (long)AXK - (long)above;
    unsigned m = 0;
    #pragma unroll
    for (int s = 0; s < SEG; s++) m += cnts[s];
    if (j <= 0)               { if (tid == 0) g_thr[ns] = g_hi[ns] + 1u; return; }
    if ((unsigned long)j > m) { if (tid == 0) g_thr[ns] = g_lo[ns] + 1u; return; }
    unsigned lo = g_lo[ns], width = g_hi[ns] - lo;
    const unsigned* cand = g_cand + (size_t)ns * CAPI;

    // find target bucket B and rank r within it
    suffix256(hist, tid);
    unsigned sufd  = hist[tid];
    unsigned sufd1 = (tid < 255) ? hist[tid + 1] : 0u;
    if ((long)sufd >= j && (long)sufd1 < j) s_d = (unsigned)tid;
    __syncthreads();
    unsigned B = s_d;
    unsigned r = (unsigned)(j - (long)((B < 255) ? hist[B + 1] : 0u));
    __syncthreads();

    // single pass: collect bucket-B values into shared
    for (int s = 0; s < SEG; s++) {
        unsigned cnt = cnts[s];
        const unsigned* segp = cand + s * CAPB;
        for (unsigned idx = tid; idx < cnt; idx += 256) {
            unsigned v = segp[idx];
            if (bucket_of(v, lo, width) == B) {
                unsigned pos = atomicAdd(&s_cnt, 1u);
                if (pos < SELCAP) sbuf[pos] = v;
            }
        }
    }
    __syncthreads();
    unsigned mc = s_cnt;

    if (mc <= SELCAP) {
        // exact r-th largest among mc shared values: 4-round radix
        unsigned prefix = 0, rank = r;
        for (int shift = 24; shift >= 0; shift -= 8) {
            __syncthreads();
            hist[tid] = 0;
            __syncthreads();
            unsigned hmask = (shift == 24) ? 0u : (0xFFFFFFFFu << (shift + 8));
            for (unsigned idx = tid; idx < mc; idx += 256) {
                unsigned v = sbuf[idx];
                if ((v & hmask) == prefix) atomicAdd(&hist[(v >> shift) & 255u], 1u);
            }
            __syncthreads();
            suffix256(hist, tid);
            unsigned sd  = hist[tid];
            unsigned sd1 = (tid < 255) ? hist[tid + 1] : 0u;
            if (sd >= rank && sd1 < rank) s_d = (unsigned)tid;
            __syncthreads();
            unsigned d = s_d;
            rank -= (d < 255) ? hist[d + 1] : 0u;
            prefix |= d << shift;
        }
        if (tid == 0) g_thr[ns] = prefix;
    } else {
        // fallback (essentially never): 4-round radix over all candidates
        unsigned prefix = 0, rank = (unsigned)j;
        for (int shift = 24; shift >= 0; shift -= 8) {
            __syncthreads();
            hist[tid] = 0;
            __syncthreads();
            unsigned hmask = (shift == 24) ? 0u : (0xFFFFFFFFu << (shift + 8));
            for (int s = 0; s < SEG; s++) {
                unsigned cnt = cnts[s];
                const unsigned* segp = cand + s * CAPB;
                for (unsigned idx = tid; idx < cnt; idx += 256) {
                    unsigned v = segp[idx];
                    if ((v & hmask) == prefix) atomicAdd(&hist[(v >> shift) & 255u], 1u);
                }
            }
            __syncthreads();
            suffix256(hist, tid);
            unsigned sd  = hist[tid];
            unsigned sd1 = (tid < 255) ? hist[tid + 1] : 0u;
            if (sd >= rank && sd1 < rank) s_d = (unsigned)tid;
            __syncthreads();
            unsigned d = s_d;
            rank -= (d < 255) ? hist[d + 1] : 0u;
            prefix |= d << shift;
        }
        if (tid == 0) g_thr[ns] = prefix;
    }
}

// ---------------- K4: fused scatter-scan, one row per block (512 blocks) -----
__global__ void __launch_bounds__(256) k_scan(const float* __restrict__ tgt,
                                              const float* __restrict__ prd) {
    __shared__ unsigned shT[NIMG], shP[NIMG];
    __shared__ float fred[8];
    int tid = threadIdx.x, lane = tid & 31;
    if (tid < NIMG) shT[tid] = g_thr[tid];
    else            shP[tid - NIMG] = g_thr[tid];
    __syncthreads();

    int i = blockIdx.x;               // row
    int j = tid * 2;                  // column of first pixel
    bool lastrow = (i == 511);
    bool edge31 = (lane == 31);
    bool lastcol = (j == 510);
    int p = i * 512 + j;
    const float* tp = tgt + p;
    const float* pp = prd + p;
    float etf0 = 0.f, etf1 = 0.f, epf0 = 0.f, epf1 = 0.f, acc = 0.f;

    #pragma unroll 4
    for (int n = 0; n < NIMG; n++) {
        float2 t0 = __ldg((const float2*)tp);
        float2 t1 = lastrow ? make_float2(0.f, 0.f) : __ldg((const float2*)(tp + 512));
        float2 p0 = __ldg((const float2*)pp);
        float2 p1 = lastrow ? make_float2(0.f, 0.f) : __ldg((const float2*)(pp + 512));
        float tx2 = __shfl_down_sync(0xffffffffu, t0.x, 1);
        float ty2 = __shfl_down_sync(0xffffffffu, t1.x, 1);
        float px2 = __shfl_down_sync(0xffffffffu, p0.x, 1);
        float py2 = __shfl_down_sync(0xffffffffu, p1.x, 1);
        if (edge31) {
            tx2 = lastcol ? 0.f : __ldg(tp + 2);
            ty2 = (lastcol || lastrow) ? 0.f : __ldg(tp + 514);
            px2 = lastcol ? 0.f : __ldg(pp + 2);
            py2 = (lastcol || lastrow) ? 0.f : __ldg(pp + 514);
        }
        float mt0 = m2_one(t0.x, t0.y, t1.x, t1.y);
        float mt1 = m2_one(t0.y, tx2, t1.y, ty2);
        float mp0 = m2_one(p0.x, p0.y, p1.x, p1.y);
        float mp1 = m2_one(p0.y, px2, p1.y, py2);
        unsigned thT = shT[n], thP = shP[n];
        if (__float_as_uint(mt0) >= thT) etf0 = sqrtf(mt0);
        if (__float_as_uint(mt1) >= thT) etf1 = sqrtf(mt1);
        if (__float_as_uint(mp0) >= thP) epf0 = sqrtf(mp0);
        if (__float_as_uint(mp1) >= thP) epf1 = sqrtf(mp1);
        acc += __fdividef(fabsf(etf0 - epf0), etf0 + epf0 + 1e-5f);
        acc += __fdividef(fabsf(etf1 - epf1), etf1 + epf1 + 1e-5f);
        tp += HWSZ; pp += HWSZ;
    }

    #pragma unroll
    for (int o = 16; o; o >>= 1) acc += __shfl_down_sync(0xffffffffu, acc, o);
    if (lane == 0) fred[tid >> 5] = acc;
    __syncthreads();
    if (tid == 0) {
        float t = 0.0f;
        #pragma unroll
        for (int w = 0; w < 8; w++) t += fred[w];
        atomicAdd(&g_acc, (double)t);
    }
}

// ---------------- K5: finalize ----------------
__global__ void k_final(const float* __restrict__ alpha, float* __restrict__ out) {
    out[0] = (float)((double)alpha[0] * g_acc / 33554432.0);
}

extern "C" void kernel_launch(void* const* d_in, const int* in_sizes, int n_in,
                              void* d_out, int out_size) {
    const float* pred  = (const float*)d_in[0];
    const float* tgt   = (const float*)d_in[1];
    const float* alpha = (const float*)d_in[2];
    float* out = (float*)d_out;

    k_zero<<<256, 256>>>();
    k_bracket<<<dim3(NIMG, 2), 256>>>(tgt, pred);
    k_count<<<dim3(SEG, NIMG, 2), 256>>>(tgt, pred);
    k_select<<<2 * NIMG, 256>>>();
    k_scan<<<512, 256>>>(tgt, pred);
    k_final<<<1, 1>>>(alpha, out);
}

// round 5
// speedup vs baseline: 1.3087x; 1.3087x over previous
#include <cuda_runtime.h>

#define HWSZ   262144
#define NIMG   128
#define AXK    26214
#define SEG    16
#define CAPB   4096
#define CAPI   (SEG*CAPB)
#define SELCAP 3072
#define R_HI   260
#define R_LO   560

// ---------------- static scratch ----------------
__device__ unsigned g_cand[(size_t)2 * NIMG * CAPI];   // 64 MB
__device__ unsigned g_bhist[2 * NIMG * 256];
__device__ unsigned g_cnt[2 * NIMG][SEG];
__device__ unsigned g_above[2 * NIMG];
__device__ unsigned g_hi[2 * NIMG], g_lo[2 * NIMG], g_thr[2 * NIMG];
__device__ double   g_acc;

// Bit-identical squared Roberts magnitude everywhere (fixed op order).
__device__ __forceinline__ float m2_one(float a, float b, float c, float d) {
    float gx = a - d, gy = b - c;
    return fmaf(gx, gx, fmaf(gy, gy, 1e-12f));
}

__device__ __forceinline__ float asqrt(float x) {
    float r; asm("sqrt.approx.f32 %0, %1;" : "=f"(r) : "f"(x)); return r;
}

// Division-free bucket shift: buckets = delta >> s fit in [0,256).
__device__ __forceinline__ unsigned bshift(unsigned width) {
    int hb = 32 - __clz(width - 1u);     // bits needed for delta in [0,width)
    int s = hb - 8;
    return (s > 0) ? (unsigned)s : 0u;
}

struct Quad { float4 v0, v1; float x4, y4; };

__device__ __forceinline__ Quad load_quad(const float* __restrict__ img, int p, int lane) {
    Quad q;
    int i = p >> 9, j = p & 511;
    q.v0 = __ldg((const float4*)(img + p));
    bool lastrow = (i == 511);
    q.v1 = lastrow ? make_float4(0.f, 0.f, 0.f, 0.f)
                   : __ldg((const float4*)(img + p + 512));
    q.x4 = __shfl_down_sync(0xffffffffu, q.v0.x, 1);
    q.y4 = __shfl_down_sync(0xffffffffu, q.v1.x, 1);
    if (lane == 31) {
        bool hn = (j + 4) < 512;
        q.x4 = hn ? __ldg(img + p + 4) : 0.0f;
        q.y4 = (hn && !lastrow) ? __ldg(img + p + 516) : 0.0f;
    }
    return q;
}

__device__ __forceinline__ void quad_m2(const Quad& q, float m2[4]) {
    m2[0] = m2_one(q.v0.x, q.v0.y, q.v1.x, q.v1.y);
    m2[1] = m2_one(q.v0.y, q.v0.z, q.v1.y, q.v1.z);
    m2[2] = m2_one(q.v0.z, q.v0.w, q.v1.z, q.v1.w);
    m2[3] = m2_one(q.v0.w, q.x4,   q.v1.w, q.y4);
}

// suffix sum over 256 shared entries; safe for any blockDim >= 256
__device__ __forceinline__ void suffix256_all(volatile unsigned* s, int tid) {
    #pragma unroll
    for (int off = 1; off < 256; off <<= 1) {
        unsigned add = 0;
        if (tid < 256 && tid + off < 256) add = s[tid + off];
        __syncthreads();
        if (tid < 256) s[tid] += add;
        __syncthreads();
    }
}

// ---------------- K0: zero ----------------
__global__ void k_zero() {
    int t = blockIdx.x * 256 + threadIdx.x;
    if (t < 2 * NIMG * 256) g_bhist[t] = 0;
    if (t < 2 * NIMG * SEG) ((unsigned*)g_cnt)[t] = 0;
    if (t < 2 * NIMG) g_above[t] = 0;
    if (t == 0) g_acc = 0.0;
}

// ---------------- K1: sampled bracket (4096 samples, 4-round radix) ----------
__global__ void k_bracket(const float* __restrict__ tgt, const float* __restrict__ prd) {
    __shared__ unsigned sval[4096];
    __shared__ unsigned hist[256];
    __shared__ unsigned s_d;
    int n = blockIdx.x, sel = blockIdx.y;
    const float* img = (sel ? prd : tgt) + (size_t)n * HWSZ;
    int tid = threadIdx.x, lane = tid & 31, wid = tid >> 5;

    #pragma unroll
    for (int k = 0; k < 4; k++) {
        int c   = k * 8 + wid;
        int row = (c * 509) & 511;
        int col = (c & 3) * 128;
        int p   = row * 512 + col + lane * 4;
        Quad q = load_quad(img, p, lane);
        float m2[4]; quad_m2(q, m2);
        int s = c * 128 + lane * 4;
        sval[s + 0] = __float_as_uint(m2[0]);
        sval[s + 1] = __float_as_uint(m2[1]);
        sval[s + 2] = __float_as_uint(m2[2]);
        sval[s + 3] = __float_as_uint(m2[3]);
    }
    __syncthreads();

    unsigned res[2]; const int ranks[2] = { R_HI, R_LO };
    for (int r = 0; r < 2; r++) {
        unsigned prefix = 0, rank = (unsigned)ranks[r];
        for (int shift = 24; shift >= 0; shift -= 8) {
            hist[tid] = 0;
            __syncthreads();
            unsigned hmask = (shift == 24) ? 0u : (0xFFFFFFFFu << (shift + 8));
            #pragma unroll
            for (int k = 0; k < 16; k++) {
                unsigned v = sval[k * 256 + tid];
                if ((v & hmask) == prefix) atomicAdd(&hist[(v >> shift) & 255u], 1u);
            }
            __syncthreads();
            suffix256_all(hist, tid);
            unsigned sufd  = hist[tid];
            unsigned sufd1 = (tid < 255) ? hist[tid + 1] : 0u;
            if (sufd >= rank && sufd1 < rank) s_d = (unsigned)tid;
            __syncthreads();
            unsigned d = s_d;
            rank -= (d < 255) ? hist[d + 1] : 0u;
            prefix |= d << shift;
            __syncthreads();
        }
        res[r] = prefix;
    }
    if (tid == 0) {
        int ns = sel * NIMG + n;
        g_hi[ns] = res[0];
        g_lo[ns] = res[1];
    }
}

// ---------------- K2: count above-hi + compaction + shift-bucket hist --------
__global__ void __launch_bounds__(256) k_count(const float* __restrict__ tgt,
                                               const float* __restrict__ prd) {
    __shared__ unsigned scnt;
    __shared__ unsigned sred[8];
    __shared__ unsigned shist[256];
    int seg = blockIdx.x, n = blockIdx.y, sel = blockIdx.z;
    int ns = sel * NIMG + n;
    const float* img = (sel ? prd : tgt) + (size_t)n * HWSZ;
    unsigned hi = g_hi[ns], lo = g_lo[ns];
    unsigned width = hi - lo;
    unsigned s = bshift(width | 1u);
    int tid = threadIdx.x, lane = tid & 31;
    if (tid == 0) scnt = 0;
    shist[tid] = 0;
    __syncthreads();
    unsigned* seg_out = g_cand + (size_t)ns * CAPI + (size_t)seg * CAPB;
    unsigned above = 0;
    int base = seg * (HWSZ / SEG);

    #pragma unroll 2
    for (int it = 0; it < (HWSZ / SEG) / 1024; it++) {
        int p = base + it * 1024 + tid * 4;
        Quad q = load_quad(img, p, lane);
        float m2[4]; quad_m2(q, m2);
        unsigned vb[4], c = 0; bool isc[4];
        #pragma unroll
        for (int k = 0; k < 4; k++) {
            vb[k] = __float_as_uint(m2[k]);
            above += (vb[k] > hi);
            isc[k] = (vb[k] > lo) && (vb[k] <= hi);
            c += isc[k];
        }
        unsigned inc = c;
        #pragma unroll
        for (int o = 1; o < 32; o <<= 1) {
            unsigned t = __shfl_up_sync(0xffffffffu, inc, o);
            if (lane >= o) inc += t;
        }
        unsigned tot = __shfl_sync(0xffffffffu, inc, 31);
        if (tot) {
            unsigned bb = 0;
            if (lane == 31) bb = atomicAdd(&scnt, tot);
            bb = __shfl_sync(0xffffffffu, bb, 31);
            unsigned off = bb + inc - c;
            #pragma unroll
            for (int k = 0; k < 4; k++)
                if (isc[k]) {
                    if (off < CAPB) {
                        seg_out[off] = vb[k];
                        atomicAdd(&shist[(vb[k] - lo - 1u) >> s], 1u);
                    }
                    off++;
                }
        }
    }
    #pragma unroll
    for (int o = 16; o; o >>= 1) above += __shfl_down_sync(0xffffffffu, above, o);
    if (lane == 0) sred[tid >> 5] = above;
    __syncthreads();
    if (shist[tid]) atomicAdd(&g_bhist[ns * 256 + tid], shist[tid]);
    if (tid == 0) {
        unsigned t = 0;
        #pragma unroll
        for (int w = 0; w < 8; w++) t += sred[w];
        atomicAdd(&g_above[ns], t);
        g_cnt[ns][seg] = min(scnt, (unsigned)CAPB);
    }
}

// ---------------- K3: exact select — hist lookup + one stream + O(k^2) rank --
__global__ void __launch_bounds__(1024) k_select() {
    __shared__ unsigned hist[256];
    __shared__ unsigned sbuf[SELCAP];
    __shared__ unsigned cnts[SEG];
    __shared__ unsigned s_d, s_cnt, s_ans;
    int ns = blockIdx.x, tid = threadIdx.x;
    if (tid < SEG) cnts[tid] = min(g_cnt[ns][tid], (unsigned)CAPB);
    if (tid == 0) { s_cnt = 0; }
    if (tid < 256) hist[tid] = g_bhist[ns * 256 + tid];
    __syncthreads();
    unsigned above = g_above[ns];
    long j = (long)AXK - (long)above;
    unsigned m = 0;
    #pragma unroll
    for (int ss = 0; ss < SEG; ss++) m += cnts[ss];
    if (j <= 0)               { if (tid == 0) g_thr[ns] = g_hi[ns] + 1u; return; }
    if ((unsigned long)j > m) { if (tid == 0) g_thr[ns] = g_lo[ns] + 1u; return; }
    unsigned lo = g_lo[ns], width = g_hi[ns] - lo;
    unsigned s = bshift(width | 1u);
    const unsigned* cand = g_cand + (size_t)ns * CAPI;

    // target bucket B and in-bucket rank r
    suffix256_all(hist, tid);
    if (tid < 256) {
        unsigned sufd  = hist[tid];
        unsigned sufd1 = (tid < 255) ? hist[tid + 1] : 0u;
        if ((long)sufd >= j && (long)sufd1 < j) s_d = (unsigned)tid;
    }
    __syncthreads();
    unsigned B = s_d;
    unsigned r = (unsigned)(j - (long)((B < 255) ? hist[B + 1] : 0u));
    __syncthreads();

    // single coalesced stream: keep bucket-B values (2 ALU ops per value)
    #pragma unroll
    for (int sg = 0; sg < SEG; sg++) {
        unsigned cnt = cnts[sg];
        const unsigned* segp = cand + sg * CAPB;
        for (unsigned idx = tid; idx < cnt; idx += 1024) {
            unsigned v = segp[idx];
            if (((v - lo - 1u) >> s) == B) {
                unsigned pos = atomicAdd(&s_cnt, 1u);
                if (pos < SELCAP) sbuf[pos] = v;
            }
        }
    }
    __syncthreads();
    unsigned mc = s_cnt;

    if (mc <= SELCAP) {
        // exact r-th largest among mc values: rank by broadcast compare
        for (unsigned i = tid; i < mc; i += 1024) {
            unsigned v = sbuf[i], gt = 0, ge = 0;
            for (unsigned jx = 0; jx < mc; jx++) {
                unsigned u = sbuf[jx];
                gt += (u > v); ge += (u >= v);
            }
            if (gt < r && r <= ge) s_ans = v;
        }
        __syncthreads();
        if (tid == 0) g_thr[ns] = s_ans;
    } else {
        // fallback (practically never): radix over remaining delta bits
        unsigned pref = B << s, rank = r;
        int sh = (int)s;
        while (sh > 0) {
            int nsh = sh - 8; if (nsh < 0) nsh = 0;
            unsigned w = (unsigned)(sh - nsh);
            unsigned known = ~((1u << sh) - 1u);
            __syncthreads();
            if (tid < 256) hist[tid] = 0;
            __syncthreads();
            for (int sg = 0; sg < SEG; sg++) {
                unsigned cnt = cnts[sg];
                const unsigned* segp = cand + sg * CAPB;
                for (unsigned idx = tid; idx < cnt; idx += 1024) {
                    unsigned d = segp[idx] - lo - 1u;
                    if ((d & known) == pref)
                        atomicAdd(&hist[(d >> nsh) & ((1u << w) - 1u)], 1u);
                }
            }
            __syncthreads();
            suffix256_all(hist, tid);
            if (tid < 256) {
                unsigned sd  = hist[tid];
                unsigned sd1 = (tid < 255) ? hist[tid + 1] : 0u;
                if (sd >= rank && sd1 < rank) s_d = (unsigned)tid;
            }
            __syncthreads();
            unsigned d = s_d;
            rank -= (d < 255) ? hist[d + 1] : 0u;
            pref |= d << nsh;
            sh = nsh;
            __syncthreads();
        }
        if (tid == 0) g_thr[ns] = lo + 1u + pref;
    }
}

// ---------------- K4: fused scatter-scan, 64-thr blocks, 4px/thread ----------
__global__ void __launch_bounds__(64) k_scan(const float* __restrict__ tgt,
                                             const float* __restrict__ prd) {
    __shared__ unsigned shT[NIMG], shP[NIMG];
    __shared__ float fred[2];
    int tid = threadIdx.x, lane = tid & 31;
    for (int k = tid; k < 2 * NIMG; k += 64) {
        unsigned v = g_thr[k];
        if (k < NIMG) shT[k] = v; else shP[k - NIMG] = v;
    }
    __syncthreads();

    int p = (blockIdx.x * 64 + tid) * 4;
    float etf[4] = {0.f,0.f,0.f,0.f}, epf[4] = {0.f,0.f,0.f,0.f};
    float acc = 0.0f;

    #pragma unroll 2
    for (int n = 0; n < NIMG; n++) {
        Quad qt = load_quad(tgt + (size_t)n * HWSZ, p, lane);
        Quad qp = load_quad(prd + (size_t)n * HWSZ, p, lane);
        float mt[4], mp[4];
        quad_m2(qt, mt); quad_m2(qp, mp);
        unsigned thT = shT[n], thP = shP[n];
        #pragma unroll
        for (int k = 0; k < 4; k++) {
            if (__float_as_uint(mt[k]) >= thT) etf[k] = asqrt(mt[k]);
            if (__float_as_uint(mp[k]) >= thP) epf[k] = asqrt(mp[k]);
            acc += __fdividef(fabsf(etf[k] - epf[k]), etf[k] + epf[k] + 1e-5f);
        }
    }

    #pragma unroll
    for (int o = 16; o; o >>= 1) acc += __shfl_down_sync(0xffffffffu, acc, o);
    if (lane == 0) fred[tid >> 5] = acc;
    __syncthreads();
    if (tid == 0) atomicAdd(&g_acc, (double)(fred[0] + fred[1]));
}

// ---------------- K5: finalize ----------------
__global__ void k_final(const float* __restrict__ alpha, float* __restrict__ out) {
    out[0] = (float)((double)alpha[0] * g_acc / 33554432.0);
}

extern "C" void kernel_launch(void* const* d_in, const int* in_sizes, int n_in,
                              void* d_out, int out_size) {
    const float* pred  = (const float*)d_in[0];
    const float* tgt   = (const float*)d_in[1];
    const float* alpha = (const float*)d_in[2];
    float* out = (float*)d_out;

    k_zero<<<256, 256>>>();
    k_bracket<<<dim3(NIMG, 2), 256>>>(tgt, pred);
    k_count<<<dim3(SEG, NIMG, 2), 256>>>(tgt, pred);
    k_select<<<2 * NIMG, 1024>>>();
    k_scan<<<HWSZ / 256, 64>>>(tgt, pred);
    k_final<<<1, 1>>>(alpha, out);
}